// round 6
// baseline (speedup 1.0000x reference)
#include <cuda_runtime.h>
#include <math.h>

#define Bn 8
#define Hn 256
#define Wn 256
#define NPIX (Bn*Hn*Wn)       // 524288
#define INF_F 1e10f
#define RW 4                  // window radius; accept bound (RW+1)^2 = 25
#define RW_BOUND ((RW+1)*(RW+1))
#define SR 4                  // strip rows per block
#define MR (SR + 2*RW)        // 12 halo rows per block
#define SPB (Hn/SR)           // 64 strips per batch
#define NBLK (Bn * SPB)       // 512 blocks

// Per-block partials (disjoint coverage -> no atomics on data, deterministic)
__device__ float  d_spt[NBLK];
__device__ float  d_sp2[NBLK];
__device__ float  d_st [NBLK];
__device__ double d_bnd[NBLK];
__device__ unsigned d_cnt = 0;   // last-block-done counter (reset by last block)

// Distance (clamped to 7) from offset-0 (bit 15) to nearest set bit of v.
__device__ __forceinline__ int win_dist(unsigned v) {
    unsigned left = v << 16;                 // bit 31-d = offset -d
    int dl = left ? __clz(left) : 99;
    unsigned right = v >> 15;                // bit d = offset +d
    int dr = right ? (__ffs(right) - 1) : 99;
    return min(min(dl, dr), 7);
}

// Exact global fallback (bitwise-matches reference min-plus; never taken for
// benign inputs, preserves worst-case exactness).
__device__ __noinline__ float fb_min(const float* __restrict__ timg,
                                     int i, int w, bool want_one) {
    float m = 3.0e38f;
    for (int j = 0; j < Hn; j++) {
        int best = 1 << 20;
        for (int c = 0; c < Wn; c++) {
            float tv = timg[j * Wn + c];
            bool hit = want_one ? (tv > 0.5f) : (tv <= 0.5f);
            if (hit) best = min(best, abs(w - c));
        }
        float g = (best < Wn) ? (float)(best * best) : INF_F;
        float dj = (float)(i - j);
        m = fminf(m, fmaf(dj, dj, g));
    }
    return m;
}

__global__ void __launch_bounds__(256) fused_kernel(
        const float* __restrict__ pred,
        const float* __restrict__ target,
        const int* __restrict__ flg,
        float* __restrict__ out) {
    __shared__ unsigned msk[MR][8];
    __shared__ float rsf[3][8];
    __shared__ double rsd[8];
    __shared__ unsigned is_last_sh;

    int tid  = threadIdx.x;
    int lane = tid & 31, wwp = tid >> 5;
    int b    = blockIdx.x >> 6;              // batch
    int i0   = (blockIdx.x & 63) * SR;       // strip start row
    int j0   = i0 - RW;
    const float* timg = target + (size_t)b * Hn * Wn;
    int fl = flg[0];

    // --- target bitmasks for the 12 halo rows (warp wwp: rows wwp, wwp+8)
    for (int r = wwp; r < MR; r += 8) {
        int j = j0 + r;
        if ((unsigned)j < (unsigned)Hn) {
            #pragma unroll
            for (int seg = 0; seg < 8; seg++) {
                float tv = timg[j * Wn + seg * 32 + lane];
                unsigned bal = __ballot_sync(0xffffffffu, tv > 0.5f);
                if (lane == 0) msk[r][seg] = bal;
            }
        }
    }

    // prefetch pred for this thread's column (overlaps mask-phase latency)
    int w = tid;
    float pv[SR];
    #pragma unroll
    for (int k = 0; k < SR; k++)
        pv[k] = pred[(((size_t)b * Hn) + i0 + k) * Wn + w];

    __syncthreads();

    // --- per-column clamped row distances, packed dx^2 | dy^2<<16 (REGISTERS)
    int ww = w >> 5, bb = w & 31;
    unsigned g[MR];
    #pragma unroll
    for (int r = 0; r < MR; r++) {
        int j = j0 + r;
        if ((unsigned)j < (unsigned)Hn) {
            const unsigned* m = msk[r];
            unsigned mw = m[ww];
            unsigned lo = (ww >= 1) ? m[ww - 1] : 0u;
            unsigned hi = (ww <= 6) ? m[ww + 1] : 0u;
            unsigned v, vm;
            if (bb >= 15) {
                v  = __funnelshift_r(mw, hi, bb - 15);
                vm = __funnelshift_r(0xffffffffu, (ww <= 6) ? 0xffffffffu : 0u, bb - 15);
            } else {
                v  = __funnelshift_r(lo, mw, bb + 17);
                vm = __funnelshift_r((ww >= 1) ? 0xffffffffu : 0u, 0xffffffffu, bb + 17);
            }
            int dx = win_dist(v);               // dist to nearest 1
            int dy = win_dist((~v) & vm);       // dist to nearest 0
            g[r] = (unsigned)(dx * dx) | ((unsigned)(dy * dy) << 16);
        } else {
            g[r] = 49u | (49u << 16);           // >= 49: never accepted
        }
    }

    // --- windowed column pass + dice + boundary (all register-resident)
    float spt = 0.f, sp2 = 0.f, stt = 0.f;
    double bsum = 0.0;

    #pragma unroll
    for (int k = 0; k < SR; k++) {
        unsigned m = g[k] + ((RW * RW) | ((RW * RW) << 16));
        #pragma unroll
        for (int u = 1; u <= 2 * RW; u++) {
            int q = (u - RW) * (u - RW);
            m = __vminu2(m, g[k + u] + (unsigned)(q | (q << 16)));
        }
        int mo = (int)(m & 0xffffu);
        int mi = (int)(m >> 16);
        int i = i0 + k;
        // window min <= 25 is provably the exact global min (outside >= 25)
        float fmo = (mo <= RW_BOUND) ? (float)mo : fb_min(timg, i, w, true);
        float fmi = (mi <= RW_BOUND) ? (float)mi : fb_min(timg, i, w, false);
        float dist = sqrtf(fmo) + sqrtf(fmi);

        float p = pv[k];
        if (fl) p = __fdividef(1.0f, 1.0f + __expf(-p));
        float tb = (float)((msk[k + RW][ww] >> bb) & 1u);

        spt += p * tb;
        sp2 += p * p;
        stt += tb;
        bsum += (double)(p * dist);
    }

    // --- block reduction
    #pragma unroll
    for (int o = 16; o; o >>= 1) {
        spt  += __shfl_down_sync(0xffffffffu, spt,  o);
        sp2  += __shfl_down_sync(0xffffffffu, sp2,  o);
        stt  += __shfl_down_sync(0xffffffffu, stt,  o);
        bsum += __shfl_down_sync(0xffffffffu, bsum, o);
    }
    if (lane == 0) { rsf[0][wwp] = spt; rsf[1][wwp] = sp2; rsf[2][wwp] = stt; rsd[wwp] = bsum; }
    __syncthreads();

    if (tid == 0) {
        float A = 0.f, Bv = 0.f, C = 0.f; double D = 0.0;
        #pragma unroll
        for (int q = 0; q < 8; q++) { A += rsf[0][q]; Bv += rsf[1][q]; C += rsf[2][q]; D += rsd[q]; }
        d_spt[blockIdx.x] = A; d_sp2[blockIdx.x] = Bv; d_st[blockIdx.x] = C;
        d_bnd[blockIdx.x] = D;
        __threadfence();
        unsigned prev = atomicAdd(&d_cnt, 1u);
        is_last_sh = (prev == NBLK - 1) ? 1u : 0u;
    }
    __syncthreads();

    // --- last block finalizes (no extra kernel)
    if (is_last_sh) {
        __shared__ double dsh[8], bsh[8];
        // dice: warp wwp reduces batch wwp's 64 strip-partials (2 per lane)
        int blk = wwp * SPB + lane;
        double a  = (double)__ldcg(&d_spt[blk]) + (double)__ldcg(&d_spt[blk + 32]);
        double bv = (double)__ldcg(&d_sp2[blk]) + (double)__ldcg(&d_sp2[blk + 32]);
        double c  = (double)__ldcg(&d_st [blk]) + (double)__ldcg(&d_st [blk + 32]);
        #pragma unroll
        for (int o = 16; o; o >>= 1) {
            a  += __shfl_down_sync(0xffffffffu, a,  o);
            bv += __shfl_down_sync(0xffffffffu, bv, o);
            c  += __shfl_down_sync(0xffffffffu, c,  o);
        }
        if (lane == 0) dsh[wwp] = 1.0 - (2.0 * a + 1e-6) / (bv + c + 1e-6);

        // boundary: 512 partials across 256 threads (2 each)
        double bd = __ldcg(&d_bnd[tid]) + __ldcg(&d_bnd[tid + 256]);
        #pragma unroll
        for (int o = 16; o; o >>= 1)
            bd += __shfl_down_sync(0xffffffffu, bd, o);
        if (lane == 0) bsh[wwp] = bd;
        __syncthreads();

        if (tid == 0) {
            double d = 0.0, bbv = 0.0;
            #pragma unroll
            for (int q = 0; q < 8; q++) { d += dsh[q]; bbv += bsh[q]; }
            out[0] = (float)(d * (1.0 / (double)Bn) + bbv * (1.0 / (double)NPIX));
            d_cnt = 0;   // reset for next graph replay (deterministic)
        }
    }
}

extern "C" void kernel_launch(void* const* d_in, const int* in_sizes, int n_in,
                              void* d_out, int out_size) {
    const float* pred   = (const float*)d_in[0];
    const float* target = (const float*)d_in[1];
    const int*   flg    = (const int*)d_in[2];
    float* out = (float*)d_out;

    fused_kernel<<<NBLK, 256>>>(pred, target, flg, out);
}